// round 14
// baseline (speedup 1.0000x reference)
#include <cuda_runtime.h>

#define N_USERS 100000
#define N_ITEMS 50000
#define NNZ     1600000
#define DIM     64
#define N_TOT   (N_USERS + N_ITEMS)          // 150000 destination rows
#define SCAN_NB ((N_TOT + 255) / 256)        // 586 scan blocks

// ---------------------------------------------------------------------------
// Device-global scratch (no allocation allowed).
// ---------------------------------------------------------------------------
__device__ float g_xw_user[N_USERS * DIM];
__device__ float g_xw_item[N_ITEMS * DIM];
__device__ int   g_cnt[N_TOT];               // per-destination edge count
__device__ int   g_off[N_TOT];               // exclusive-scan offsets
__device__ int   g_cur[N_TOT];               // fill cursors (copy of offsets)
__device__ int   g_bsum[1024];               // scan block sums
__device__ unsigned long long g_csr[2 * NNZ];// packed (idx | val<<32) adjacency

__device__ __forceinline__ void fma4(float4& acc, float s, float4 w) {
    acc.x = fmaf(s, w.x, acc.x);
    acc.y = fmaf(s, w.y, acc.y);
    acc.z = fmaf(s, w.z, acc.z);
    acc.w = fmaf(s, w.w, acc.w);
}

// ---------------------------------------------------------------------------
// Dense projection, 4x4 register tiling (measured-good version, zero-fusion
// removed: the gather kernel writes every output element).
// ---------------------------------------------------------------------------
__global__ __launch_bounds__(256) void gemm64_tiled_kernel(
        const float* __restrict__ x,
        const float* __restrict__ W,
        float* __restrict__ out, int M) {
    __shared__ float4 sW[DIM * 16];
    int tid = threadIdx.x;
    #pragma unroll
    for (int i = 0; i < 4; i++)
        sW[tid + i * 256] = reinterpret_cast<const float4*>(W)[tid + i * 256];
    __syncthreads();

    int rg  = tid >> 4;
    int c4  = tid & 15;
    int row0 = blockIdx.x * 64 + rg * 4;

    const float4* xr0 = reinterpret_cast<const float4*>(x + (size_t)row0 * DIM);
    bool v0 = (row0 + 0) < M, v1 = (row0 + 1) < M,
         v2 = (row0 + 2) < M, v3 = (row0 + 3) < M;

    float4 a0 = make_float4(0,0,0,0), a1 = a0, a2 = a0, a3 = a0;

    #pragma unroll
    for (int k4 = 0; k4 < 16; k4++) {
        float4 x0 = v0 ? xr0[k4]      : make_float4(0,0,0,0);
        float4 x1 = v1 ? xr0[16 + k4] : make_float4(0,0,0,0);
        float4 x2 = v2 ? xr0[32 + k4] : make_float4(0,0,0,0);
        float4 x3 = v3 ? xr0[48 + k4] : make_float4(0,0,0,0);

        float4 w0 = sW[(k4 * 4 + 0) * 16 + c4];
        fma4(a0, x0.x, w0); fma4(a1, x1.x, w0); fma4(a2, x2.x, w0); fma4(a3, x3.x, w0);
        float4 w1 = sW[(k4 * 4 + 1) * 16 + c4];
        fma4(a0, x0.y, w1); fma4(a1, x1.y, w1); fma4(a2, x2.y, w1); fma4(a3, x3.y, w1);
        float4 w2 = sW[(k4 * 4 + 2) * 16 + c4];
        fma4(a0, x0.z, w2); fma4(a1, x1.z, w2); fma4(a2, x2.z, w2); fma4(a3, x3.z, w2);
        float4 w3 = sW[(k4 * 4 + 3) * 16 + c4];
        fma4(a0, x0.w, w3); fma4(a1, x1.w, w3); fma4(a2, x2.w, w3); fma4(a3, x3.w, w3);
    }

    float4* o4 = reinterpret_cast<float4*>(out) + (size_t)row0 * 16 + c4;
    if (v0) o4[0]  = a0;
    if (v1) o4[16] = a1;
    if (v2) o4[32] = a2;
    if (v3) o4[48] = a3;
}

// ---------------------------------------------------------------------------
// CSR build: zero counts -> histogram -> exclusive scan (3 kernels) -> fill.
// Combined index space: destinations [0,100000) are users, [100000,150000) items.
// ---------------------------------------------------------------------------
__global__ void zero_counts_kernel() {
    int i = blockIdx.x * blockDim.x + threadIdx.x;
    if (i < N_TOT) g_cnt[i] = 0;
}

__global__ void hist_kernel(const int* __restrict__ rows,
                            const int* __restrict__ cols) {
    int e = blockIdx.x * blockDim.x + threadIdx.x;
    if (e >= NNZ) return;
    atomicAdd(&g_cnt[rows[e]], 1);
    atomicAdd(&g_cnt[N_USERS + cols[e]], 1);
}

// Per-block exclusive scan of 256 counts; writes within-block prescan + block sum.
__global__ void scan1_kernel() {
    __shared__ int s[256];
    int i = blockIdx.x * 256 + threadIdx.x;
    int v = (i < N_TOT) ? g_cnt[i] : 0;
    s[threadIdx.x] = v;
    __syncthreads();
    #pragma unroll
    for (int d = 1; d < 256; d <<= 1) {
        int t = (threadIdx.x >= d) ? s[threadIdx.x - d] : 0;
        __syncthreads();
        s[threadIdx.x] += t;
        __syncthreads();
    }
    int incl = s[threadIdx.x];
    if (i < N_TOT) g_off[i] = incl - v;          // exclusive within block
    if (threadIdx.x == 255) g_bsum[blockIdx.x] = incl;
}

// Single-block exclusive scan of the block sums (SCAN_NB = 586 <= 1024).
__global__ void scan2_kernel() {
    __shared__ int s[1024];
    int t = threadIdx.x;
    int v = (t < SCAN_NB) ? g_bsum[t] : 0;
    s[t] = v;
    __syncthreads();
    #pragma unroll
    for (int d = 1; d < 1024; d <<= 1) {
        int u = (t >= d) ? s[t - d] : 0;
        __syncthreads();
        s[t] += u;
        __syncthreads();
    }
    if (t < SCAN_NB) g_bsum[t] = s[t] - v;       // exclusive
}

// Add scanned block sums; initialize cursors.
__global__ void scan3_kernel() {
    int i = blockIdx.x * 256 + threadIdx.x;
    if (i >= N_TOT) return;
    int o = g_off[i] + g_bsum[blockIdx.x];
    g_off[i] = o;
    g_cur[i] = o;
}

// Fill packed CSR: each edge appends (peer, val) to both destination segments.
__global__ void fill_kernel(const int*   __restrict__ rows,
                            const int*   __restrict__ cols,
                            const float* __restrict__ vals) {
    int e = blockIdx.x * blockDim.x + threadIdx.x;
    if (e >= NNZ) return;
    int   r = rows[e];
    int   c = cols[e];
    unsigned int vb = __float_as_uint(vals[e]);

    int su = atomicAdd(&g_cur[r], 1);
    g_csr[su] = (unsigned long long)(unsigned int)c |
                ((unsigned long long)vb << 32);

    int si = atomicAdd(&g_cur[N_USERS + c], 1);
    g_csr[si] = (unsigned long long)(unsigned int)r |
                ((unsigned long long)vb << 32);
}

// ---------------------------------------------------------------------------
// Gather SpMM with fused ReLU: one warp per destination row.
// Lane l accumulates dims [2l, 2l+2) as float2; per edge: one 8B broadcast
// csr read + one coalesced 256B row gather from the projected features.
// Writes EVERY output row (empty segments produce zeros) -> no zero/relu pass.
// ---------------------------------------------------------------------------
__global__ __launch_bounds__(256) void gather_kernel(
        float* __restrict__ out_user, float* __restrict__ out_item) {
    int w    = blockIdx.x * 8 + (threadIdx.x >> 5);   // global warp = dest row
    int lane = threadIdx.x & 31;
    if (w >= N_TOT) return;

    int start = g_off[w];
    int n     = g_cnt[w];
    const float* src = (w < N_USERS) ? g_xw_item : g_xw_user;

    float2 acc = make_float2(0.f, 0.f);
    for (int k = 0; k < n; k++) {
        unsigned long long e = g_csr[start + k];      // broadcast (same addr)
        int   idx = (int)(unsigned int)(e & 0xffffffffULL);
        float v   = __uint_as_float((unsigned int)(e >> 32));
        float2 x = *reinterpret_cast<const float2*>(&src[(size_t)idx * DIM + lane * 2]);
        acc.x = fmaf(v, x.x, acc.x);
        acc.y = fmaf(v, x.y, acc.y);
    }

    float* dst = (w < N_USERS) ? (out_user + (size_t)w * DIM)
                               : (out_item + (size_t)(w - N_USERS) * DIM);
    float2 r = make_float2(fmaxf(acc.x, 0.f), fmaxf(acc.y, 0.f));
    reinterpret_cast<float2*>(dst)[lane] = r;
}

extern "C" void kernel_launch(void* const* d_in, const int* in_sizes, int n_in,
                              void* d_out, int out_size) {
    const float* user_x      = (const float*)d_in[0];
    const float* item_x      = (const float*)d_in[1];
    const float* user_weight = (const float*)d_in[2];
    const float* item_weight = (const float*)d_in[3];
    const int*   ui_rows     = (const int*)d_in[4];
    const int*   ui_cols     = (const int*)d_in[5];
    const float* ui_vals     = (const float*)d_in[6];

    float* out_user = (float*)d_out;
    float* out_item = out_user + (size_t)N_USERS * DIM;

    float* xw_user_p;
    float* xw_item_p;
    cudaGetSymbolAddress((void**)&xw_user_p, g_xw_user);
    cudaGetSymbolAddress((void**)&xw_item_p, g_xw_item);

    // CSR build pipeline (independent of the GEMMs until gather).
    zero_counts_kernel<<<(N_TOT + 1023) / 1024, 1024>>>();
    hist_kernel<<<(NNZ + 255) / 256, 256>>>(ui_rows, ui_cols);
    scan1_kernel<<<SCAN_NB, 256>>>();
    scan2_kernel<<<1, 1024>>>();
    scan3_kernel<<<SCAN_NB, 256>>>();
    fill_kernel<<<(NNZ + 255) / 256, 256>>>(ui_rows, ui_cols, ui_vals);

    // Dense projections.
    gemm64_tiled_kernel<<<(N_USERS + 63) / 64, 256>>>(user_x, user_weight, xw_user_p, N_USERS);
    gemm64_tiled_kernel<<<(N_ITEMS + 63) / 64, 256>>>(item_x, item_weight, xw_item_p, N_ITEMS);

    // Gather SpMM + fused ReLU over all 150K destination rows.
    gather_kernel<<<(N_TOT * 32 + 255) / 256, 256>>>(out_user, out_item);
}

// round 15
// speedup vs baseline: 1.0521x; 1.0521x over previous
#include <cuda_runtime.h>

#define N_USERS 100000
#define N_ITEMS 50000
#define NNZ     1600000
#define DIM     64
#define N_TOT   (N_USERS + N_ITEMS)          // 150000 destination rows
#define SCAN_NB ((N_TOT + 255) / 256)        // 586 scan blocks

// ---------------------------------------------------------------------------
// Device-global scratch (no allocation allowed).
// ---------------------------------------------------------------------------
__device__ float g_xw_user[N_USERS * DIM];
__device__ float g_xw_item[N_ITEMS * DIM];
__device__ int   g_cnt[N_TOT];               // per-destination edge count
__device__ int   g_off[N_TOT];               // exclusive-scan offsets
__device__ int   g_cur[N_TOT];               // fill cursors (copy of offsets)
__device__ int   g_bsum[1024];               // scan block sums
__device__ unsigned long long g_csr[2 * NNZ];// packed (idx | val<<32) adjacency

__device__ __forceinline__ void fma4(float4& acc, float s, float4 w) {
    acc.x = fmaf(s, w.x, acc.x);
    acc.y = fmaf(s, w.y, acc.y);
    acc.z = fmaf(s, w.z, acc.z);
    acc.w = fmaf(s, w.w, acc.w);
}

// ---------------------------------------------------------------------------
// Dense projection, 4x4 register tiling (measured-good version).
// ---------------------------------------------------------------------------
__global__ __launch_bounds__(256) void gemm64_tiled_kernel(
        const float* __restrict__ x,
        const float* __restrict__ W,
        float* __restrict__ out, int M) {
    __shared__ float4 sW[DIM * 16];
    int tid = threadIdx.x;
    #pragma unroll
    for (int i = 0; i < 4; i++)
        sW[tid + i * 256] = reinterpret_cast<const float4*>(W)[tid + i * 256];
    __syncthreads();

    int rg  = tid >> 4;
    int c4  = tid & 15;
    int row0 = blockIdx.x * 64 + rg * 4;

    const float4* xr0 = reinterpret_cast<const float4*>(x + (size_t)row0 * DIM);
    bool v0 = (row0 + 0) < M, v1 = (row0 + 1) < M,
         v2 = (row0 + 2) < M, v3 = (row0 + 3) < M;

    float4 a0 = make_float4(0,0,0,0), a1 = a0, a2 = a0, a3 = a0;

    #pragma unroll
    for (int k4 = 0; k4 < 16; k4++) {
        float4 x0 = v0 ? xr0[k4]      : make_float4(0,0,0,0);
        float4 x1 = v1 ? xr0[16 + k4] : make_float4(0,0,0,0);
        float4 x2 = v2 ? xr0[32 + k4] : make_float4(0,0,0,0);
        float4 x3 = v3 ? xr0[48 + k4] : make_float4(0,0,0,0);

        float4 w0 = sW[(k4 * 4 + 0) * 16 + c4];
        fma4(a0, x0.x, w0); fma4(a1, x1.x, w0); fma4(a2, x2.x, w0); fma4(a3, x3.x, w0);
        float4 w1 = sW[(k4 * 4 + 1) * 16 + c4];
        fma4(a0, x0.y, w1); fma4(a1, x1.y, w1); fma4(a2, x2.y, w1); fma4(a3, x3.y, w1);
        float4 w2 = sW[(k4 * 4 + 2) * 16 + c4];
        fma4(a0, x0.z, w2); fma4(a1, x1.z, w2); fma4(a2, x2.z, w2); fma4(a3, x3.z, w2);
        float4 w3 = sW[(k4 * 4 + 3) * 16 + c4];
        fma4(a0, x0.w, w3); fma4(a1, x1.w, w3); fma4(a2, x2.w, w3); fma4(a3, x3.w, w3);
    }

    float4* o4 = reinterpret_cast<float4*>(out) + (size_t)row0 * 16 + c4;
    if (v0) o4[0]  = a0;
    if (v1) o4[16] = a1;
    if (v2) o4[32] = a2;
    if (v3) o4[48] = a3;
}

// ---------------------------------------------------------------------------
// CSR build: zero counts -> histogram -> exclusive scan (3 kernels) -> fill.
// ---------------------------------------------------------------------------
__global__ void zero_counts_kernel() {
    int i = blockIdx.x * blockDim.x + threadIdx.x;
    if (i < N_TOT) g_cnt[i] = 0;
}

__global__ void hist_kernel(const int* __restrict__ rows,
                            const int* __restrict__ cols) {
    int e = blockIdx.x * blockDim.x + threadIdx.x;
    if (e >= NNZ) return;
    atomicAdd(&g_cnt[rows[e]], 1);
    atomicAdd(&g_cnt[N_USERS + cols[e]], 1);
}

__global__ void scan1_kernel() {
    __shared__ int s[256];
    int i = blockIdx.x * 256 + threadIdx.x;
    int v = (i < N_TOT) ? g_cnt[i] : 0;
    s[threadIdx.x] = v;
    __syncthreads();
    #pragma unroll
    for (int d = 1; d < 256; d <<= 1) {
        int t = (threadIdx.x >= d) ? s[threadIdx.x - d] : 0;
        __syncthreads();
        s[threadIdx.x] += t;
        __syncthreads();
    }
    int incl = s[threadIdx.x];
    if (i < N_TOT) g_off[i] = incl - v;
    if (threadIdx.x == 255) g_bsum[blockIdx.x] = incl;
}

__global__ void scan2_kernel() {
    __shared__ int s[1024];
    int t = threadIdx.x;
    int v = (t < SCAN_NB) ? g_bsum[t] : 0;
    s[t] = v;
    __syncthreads();
    #pragma unroll
    for (int d = 1; d < 1024; d <<= 1) {
        int u = (t >= d) ? s[t - d] : 0;
        __syncthreads();
        s[t] += u;
        __syncthreads();
    }
    if (t < SCAN_NB) g_bsum[t] = s[t] - v;
}

__global__ void scan3_kernel() {
    int i = blockIdx.x * 256 + threadIdx.x;
    if (i >= N_TOT) return;
    int o = g_off[i] + g_bsum[blockIdx.x];
    g_off[i] = o;
    g_cur[i] = o;
}

__global__ void fill_kernel(const int*   __restrict__ rows,
                            const int*   __restrict__ cols,
                            const float* __restrict__ vals) {
    int e = blockIdx.x * blockDim.x + threadIdx.x;
    if (e >= NNZ) return;
    int   r = rows[e];
    int   c = cols[e];
    unsigned int vb = __float_as_uint(vals[e]);

    int su = atomicAdd(&g_cur[r], 1);
    g_csr[su] = (unsigned long long)(unsigned int)c |
                ((unsigned long long)vb << 32);

    int si = atomicAdd(&g_cur[N_USERS + c], 1);
    g_csr[si] = (unsigned long long)(unsigned int)r |
                ((unsigned long long)vb << 32);
}

// ---------------------------------------------------------------------------
// Gather SpMM with fused ReLU, 4-way edge unroll for MLP.
// One warp per destination row; lane l accumulates dims [2l, 2l+2).
// Batch of 4: 4 independent csr loads, then 4 independent 256B row gathers.
// ---------------------------------------------------------------------------
__global__ __launch_bounds__(256) void gather_kernel(
        float* __restrict__ out_user, float* __restrict__ out_item) {
    int w    = blockIdx.x * 8 + (threadIdx.x >> 5);   // global warp = dest row
    int lane = threadIdx.x & 31;
    if (w >= N_TOT) return;

    int start = g_off[w];
    int n     = g_cnt[w];
    const float* src = (w < N_USERS) ? g_xw_item : g_xw_user;

    float2 acc = make_float2(0.f, 0.f);
    const unsigned long long* csr = g_csr + start;

    int k = 0;
    for (; k + 4 <= n; k += 4) {
        // 4 independent broadcast loads (pipelined)
        unsigned long long e0 = csr[k + 0];
        unsigned long long e1 = csr[k + 1];
        unsigned long long e2 = csr[k + 2];
        unsigned long long e3 = csr[k + 3];

        int i0 = (int)(unsigned int)e0;  float v0 = __uint_as_float((unsigned int)(e0 >> 32));
        int i1 = (int)(unsigned int)e1;  float v1 = __uint_as_float((unsigned int)(e1 >> 32));
        int i2 = (int)(unsigned int)e2;  float v2 = __uint_as_float((unsigned int)(e2 >> 32));
        int i3 = (int)(unsigned int)e3;  float v3 = __uint_as_float((unsigned int)(e3 >> 32));

        // 4 independent coalesced row gathers (MLP=4)
        float2 x0 = *reinterpret_cast<const float2*>(&src[(size_t)i0 * DIM + lane * 2]);
        float2 x1 = *reinterpret_cast<const float2*>(&src[(size_t)i1 * DIM + lane * 2]);
        float2 x2 = *reinterpret_cast<const float2*>(&src[(size_t)i2 * DIM + lane * 2]);
        float2 x3 = *reinterpret_cast<const float2*>(&src[(size_t)i3 * DIM + lane * 2]);

        acc.x = fmaf(v0, x0.x, acc.x);  acc.y = fmaf(v0, x0.y, acc.y);
        acc.x = fmaf(v1, x1.x, acc.x);  acc.y = fmaf(v1, x1.y, acc.y);
        acc.x = fmaf(v2, x2.x, acc.x);  acc.y = fmaf(v2, x2.y, acc.y);
        acc.x = fmaf(v3, x3.x, acc.x);  acc.y = fmaf(v3, x3.y, acc.y);
    }
    for (; k < n; k++) {
        unsigned long long e = csr[k];
        int   idx = (int)(unsigned int)e;
        float v   = __uint_as_float((unsigned int)(e >> 32));
        float2 x = *reinterpret_cast<const float2*>(&src[(size_t)idx * DIM + lane * 2]);
        acc.x = fmaf(v, x.x, acc.x);
        acc.y = fmaf(v, x.y, acc.y);
    }

    float* dst = (w < N_USERS) ? (out_user + (size_t)w * DIM)
                               : (out_item + (size_t)(w - N_USERS) * DIM);
    float2 r = make_float2(fmaxf(acc.x, 0.f), fmaxf(acc.y, 0.f));
    reinterpret_cast<float2*>(dst)[lane] = r;
}

extern "C" void kernel_launch(void* const* d_in, const int* in_sizes, int n_in,
                              void* d_out, int out_size) {
    const float* user_x      = (const float*)d_in[0];
    const float* item_x      = (const float*)d_in[1];
    const float* user_weight = (const float*)d_in[2];
    const float* item_weight = (const float*)d_in[3];
    const int*   ui_rows     = (const int*)d_in[4];
    const int*   ui_cols     = (const int*)d_in[5];
    const float* ui_vals     = (const float*)d_in[6];

    float* out_user = (float*)d_out;
    float* out_item = out_user + (size_t)N_USERS * DIM;

    float* xw_user_p;
    float* xw_item_p;
    cudaGetSymbolAddress((void**)&xw_user_p, g_xw_user);
    cudaGetSymbolAddress((void**)&xw_item_p, g_xw_item);

    // CSR build pipeline.
    zero_counts_kernel<<<(N_TOT + 1023) / 1024, 1024>>>();
    hist_kernel<<<(NNZ + 255) / 256, 256>>>(ui_rows, ui_cols);
    scan1_kernel<<<SCAN_NB, 256>>>();
    scan2_kernel<<<1, 1024>>>();
    scan3_kernel<<<SCAN_NB, 256>>>();
    fill_kernel<<<(NNZ + 255) / 256, 256>>>(ui_rows, ui_cols, ui_vals);

    // Dense projections.
    gemm64_tiled_kernel<<<(N_USERS + 63) / 64, 256>>>(user_x, user_weight, xw_user_p, N_USERS);
    gemm64_tiled_kernel<<<(N_ITEMS + 63) / 64, 256>>>(item_x, item_weight, xw_item_p, N_ITEMS);

    // Gather SpMM + fused ReLU over all 150K destination rows.
    gather_kernel<<<(N_TOT * 32 + 255) / 256, 256>>>(out_user, out_item);
}

// round 16
// speedup vs baseline: 1.0890x; 1.0350x over previous
#include <cuda_runtime.h>

#define N_USERS 100000
#define N_ITEMS 50000
#define NNZ     1600000
#define DIM     64
#define N_TOT   (N_USERS + N_ITEMS)          // 150000 destination rows
#define SCAN_NB ((N_TOT + 255) / 256)        // 586 scan blocks

// ---------------------------------------------------------------------------
// Device-global scratch (no allocation allowed).
// g_xw: combined projected features, rows [0,N_USERS) = users, rest = items.
// ---------------------------------------------------------------------------
__device__ float g_xw[N_TOT * DIM];
__device__ int   g_cnt[N_TOT];
__device__ int   g_off[N_TOT];
__device__ int   g_cur[N_TOT];
__device__ int   g_bsum[1024];
__device__ unsigned long long g_csr[2 * NNZ];// packed (abs_src_idx | val<<32)

__device__ __forceinline__ void fma4(float4& acc, float s, float4 w) {
    acc.x = fmaf(s, w.x, acc.x);
    acc.y = fmaf(s, w.y, acc.y);
    acc.z = fmaf(s, w.z, acc.z);
    acc.w = fmaf(s, w.w, acc.w);
}

// ---------------------------------------------------------------------------
// Dense projection, 4x4 register tiling (measured-good version).
// ---------------------------------------------------------------------------
__global__ __launch_bounds__(256) void gemm64_tiled_kernel(
        const float* __restrict__ x,
        const float* __restrict__ W,
        float* __restrict__ out, int M) {
    __shared__ float4 sW[DIM * 16];
    int tid = threadIdx.x;
    #pragma unroll
    for (int i = 0; i < 4; i++)
        sW[tid + i * 256] = reinterpret_cast<const float4*>(W)[tid + i * 256];
    __syncthreads();

    int rg  = tid >> 4;
    int c4  = tid & 15;
    int row0 = blockIdx.x * 64 + rg * 4;

    const float4* xr0 = reinterpret_cast<const float4*>(x + (size_t)row0 * DIM);
    bool v0 = (row0 + 0) < M, v1 = (row0 + 1) < M,
         v2 = (row0 + 2) < M, v3 = (row0 + 3) < M;

    float4 a0 = make_float4(0,0,0,0), a1 = a0, a2 = a0, a3 = a0;

    #pragma unroll
    for (int k4 = 0; k4 < 16; k4++) {
        float4 x0 = v0 ? xr0[k4]      : make_float4(0,0,0,0);
        float4 x1 = v1 ? xr0[16 + k4] : make_float4(0,0,0,0);
        float4 x2 = v2 ? xr0[32 + k4] : make_float4(0,0,0,0);
        float4 x3 = v3 ? xr0[48 + k4] : make_float4(0,0,0,0);

        float4 w0 = sW[(k4 * 4 + 0) * 16 + c4];
        fma4(a0, x0.x, w0); fma4(a1, x1.x, w0); fma4(a2, x2.x, w0); fma4(a3, x3.x, w0);
        float4 w1 = sW[(k4 * 4 + 1) * 16 + c4];
        fma4(a0, x0.y, w1); fma4(a1, x1.y, w1); fma4(a2, x2.y, w1); fma4(a3, x3.y, w1);
        float4 w2 = sW[(k4 * 4 + 2) * 16 + c4];
        fma4(a0, x0.z, w2); fma4(a1, x1.z, w2); fma4(a2, x2.z, w2); fma4(a3, x3.z, w2);
        float4 w3 = sW[(k4 * 4 + 3) * 16 + c4];
        fma4(a0, x0.w, w3); fma4(a1, x1.w, w3); fma4(a2, x2.w, w3); fma4(a3, x3.w, w3);
    }

    float4* o4 = reinterpret_cast<float4*>(out) + (size_t)row0 * 16 + c4;
    if (v0) o4[0]  = a0;
    if (v1) o4[16] = a1;
    if (v2) o4[32] = a2;
    if (v3) o4[48] = a3;
}

// ---------------------------------------------------------------------------
// CSR build: zero counts -> histogram -> exclusive scan (3 kernels) -> fill.
// ---------------------------------------------------------------------------
__global__ void zero_counts_kernel() {
    int i = blockIdx.x * blockDim.x + threadIdx.x;
    if (i < N_TOT) g_cnt[i] = 0;
}

__global__ void hist_kernel(const int* __restrict__ rows,
                            const int* __restrict__ cols) {
    int e = blockIdx.x * blockDim.x + threadIdx.x;
    if (e >= NNZ) return;
    atomicAdd(&g_cnt[rows[e]], 1);
    atomicAdd(&g_cnt[N_USERS + cols[e]], 1);
}

__global__ void scan1_kernel() {
    __shared__ int s[256];
    int i = blockIdx.x * 256 + threadIdx.x;
    int v = (i < N_TOT) ? g_cnt[i] : 0;
    s[threadIdx.x] = v;
    __syncthreads();
    #pragma unroll
    for (int d = 1; d < 256; d <<= 1) {
        int t = (threadIdx.x >= d) ? s[threadIdx.x - d] : 0;
        __syncthreads();
        s[threadIdx.x] += t;
        __syncthreads();
    }
    int incl = s[threadIdx.x];
    if (i < N_TOT) g_off[i] = incl - v;
    if (threadIdx.x == 255) g_bsum[blockIdx.x] = incl;
}

__global__ void scan2_kernel() {
    __shared__ int s[1024];
    int t = threadIdx.x;
    int v = (t < SCAN_NB) ? g_bsum[t] : 0;
    s[t] = v;
    __syncthreads();
    #pragma unroll
    for (int d = 1; d < 1024; d <<= 1) {
        int u = (t >= d) ? s[t - d] : 0;
        __syncthreads();
        s[t] += u;
        __syncthreads();
    }
    if (t < SCAN_NB) g_bsum[t] = s[t] - v;
}

__global__ void scan3_kernel() {
    int i = blockIdx.x * 256 + threadIdx.x;
    if (i >= N_TOT) return;
    int o = g_off[i] + g_bsum[blockIdx.x];
    g_off[i] = o;
    g_cur[i] = o;
}

// Fill packed CSR with ABSOLUTE source row indices in the combined g_xw space:
// user-dest segment stores (N_USERS + c); item-dest segment stores r.
__global__ void fill_kernel(const int*   __restrict__ rows,
                            const int*   __restrict__ cols,
                            const float* __restrict__ vals) {
    int e = blockIdx.x * blockDim.x + threadIdx.x;
    if (e >= NNZ) return;
    int   r = rows[e];
    int   c = cols[e];
    unsigned long long vb = (unsigned long long)__float_as_uint(vals[e]) << 32;

    int su = atomicAdd(&g_cur[r], 1);
    g_csr[su] = vb | (unsigned int)(N_USERS + c);

    int si = atomicAdd(&g_cur[N_USERS + c], 1);
    g_csr[si] = vb | (unsigned int)r;
}

// ---------------------------------------------------------------------------
// Gather SpMM with fused ReLU, 8-way edge unroll (MLP=8).
// One warp per destination row; lane l accumulates dims [2l, 2l+2).
// Output rows are contiguous in d_out across both halves: dst = out + w*DIM.
// ---------------------------------------------------------------------------
__global__ __launch_bounds__(256) void gather_kernel(float* __restrict__ out) {
    int w    = blockIdx.x * 8 + (threadIdx.x >> 5);   // global warp = dest row
    int lane = threadIdx.x & 31;
    if (w >= N_TOT) return;

    const unsigned long long* csr = g_csr + g_off[w];
    int n = g_cnt[w];

    float2 acc = make_float2(0.f, 0.f);
    int k = 0;
    for (; k + 8 <= n; k += 8) {
        unsigned long long e0 = csr[k + 0];
        unsigned long long e1 = csr[k + 1];
        unsigned long long e2 = csr[k + 2];
        unsigned long long e3 = csr[k + 3];
        unsigned long long e4 = csr[k + 4];
        unsigned long long e5 = csr[k + 5];
        unsigned long long e6 = csr[k + 6];
        unsigned long long e7 = csr[k + 7];

        const float2* p0 = reinterpret_cast<const float2*>(&g_xw[(size_t)(unsigned int)e0 * DIM]) + lane;
        const float2* p1 = reinterpret_cast<const float2*>(&g_xw[(size_t)(unsigned int)e1 * DIM]) + lane;
        const float2* p2 = reinterpret_cast<const float2*>(&g_xw[(size_t)(unsigned int)e2 * DIM]) + lane;
        const float2* p3 = reinterpret_cast<const float2*>(&g_xw[(size_t)(unsigned int)e3 * DIM]) + lane;
        const float2* p4 = reinterpret_cast<const float2*>(&g_xw[(size_t)(unsigned int)e4 * DIM]) + lane;
        const float2* p5 = reinterpret_cast<const float2*>(&g_xw[(size_t)(unsigned int)e5 * DIM]) + lane;
        const float2* p6 = reinterpret_cast<const float2*>(&g_xw[(size_t)(unsigned int)e6 * DIM]) + lane;
        const float2* p7 = reinterpret_cast<const float2*>(&g_xw[(size_t)(unsigned int)e7 * DIM]) + lane;

        float2 x0 = *p0; float2 x1 = *p1; float2 x2 = *p2; float2 x3 = *p3;
        float2 x4 = *p4; float2 x5 = *p5; float2 x6 = *p6; float2 x7 = *p7;

        float v0 = __uint_as_float((unsigned int)(e0 >> 32));
        float v1 = __uint_as_float((unsigned int)(e1 >> 32));
        float v2 = __uint_as_float((unsigned int)(e2 >> 32));
        float v3 = __uint_as_float((unsigned int)(e3 >> 32));
        float v4 = __uint_as_float((unsigned int)(e4 >> 32));
        float v5 = __uint_as_float((unsigned int)(e5 >> 32));
        float v6 = __uint_as_float((unsigned int)(e6 >> 32));
        float v7 = __uint_as_float((unsigned int)(e7 >> 32));

        acc.x = fmaf(v0, x0.x, acc.x);  acc.y = fmaf(v0, x0.y, acc.y);
        acc.x = fmaf(v1, x1.x, acc.x);  acc.y = fmaf(v1, x1.y, acc.y);
        acc.x = fmaf(v2, x2.x, acc.x);  acc.y = fmaf(v2, x2.y, acc.y);
        acc.x = fmaf(v3, x3.x, acc.x);  acc.y = fmaf(v3, x3.y, acc.y);
        acc.x = fmaf(v4, x4.x, acc.x);  acc.y = fmaf(v4, x4.y, acc.y);
        acc.x = fmaf(v5, x5.x, acc.x);  acc.y = fmaf(v5, x5.y, acc.y);
        acc.x = fmaf(v6, x6.x, acc.x);  acc.y = fmaf(v6, x6.y, acc.y);
        acc.x = fmaf(v7, x7.x, acc.x);  acc.y = fmaf(v7, x7.y, acc.y);
    }
    for (; k < n; k++) {
        unsigned long long e = csr[k];
        float v = __uint_as_float((unsigned int)(e >> 32));
        float2 x = *(reinterpret_cast<const float2*>(&g_xw[(size_t)(unsigned int)e * DIM]) + lane);
        acc.x = fmaf(v, x.x, acc.x);
        acc.y = fmaf(v, x.y, acc.y);
    }

    float2 r = make_float2(fmaxf(acc.x, 0.f), fmaxf(acc.y, 0.f));
    reinterpret_cast<float2*>(out + (size_t)w * DIM)[lane] = r;
}

extern "C" void kernel_launch(void* const* d_in, const int* in_sizes, int n_in,
                              void* d_out, int out_size) {
    const float* user_x      = (const float*)d_in[0];
    const float* item_x      = (const float*)d_in[1];
    const float* user_weight = (const float*)d_in[2];
    const float* item_weight = (const float*)d_in[3];
    const int*   ui_rows     = (const int*)d_in[4];
    const int*   ui_cols     = (const int*)d_in[5];
    const float* ui_vals     = (const float*)d_in[6];

    float* out = (float*)d_out;

    float* xw_p;
    cudaGetSymbolAddress((void**)&xw_p, g_xw);
    float* xw_user_p = xw_p;
    float* xw_item_p = xw_p + (size_t)N_USERS * DIM;

    // CSR build pipeline.
    zero_counts_kernel<<<(N_TOT + 1023) / 1024, 1024>>>();
    hist_kernel<<<(NNZ + 255) / 256, 256>>>(ui_rows, ui_cols);
    scan1_kernel<<<SCAN_NB, 256>>>();
    scan2_kernel<<<1, 1024>>>();
    scan3_kernel<<<SCAN_NB, 256>>>();
    fill_kernel<<<(NNZ + 255) / 256, 256>>>(ui_rows, ui_cols, ui_vals);

    // Dense projections into the combined feature array.
    gemm64_tiled_kernel<<<(N_USERS + 63) / 64, 256>>>(user_x, user_weight, xw_user_p, N_USERS);
    gemm64_tiled_kernel<<<(N_ITEMS + 63) / 64, 256>>>(item_x, item_weight, xw_item_p, N_ITEMS);

    // Gather SpMM + fused ReLU over all 150K destination rows.
    gather_kernel<<<(N_TOT + 7) / 8, 256>>>(out);
}